// round 10
// baseline (speedup 1.0000x reference)
#include <cuda_runtime.h>
#include <cstdint>

// out[b, 0:128]   = emb[idx[b], :]    (128 f32)
// out[b, 128:146] = genre[idx[b], :]  (18 f32)
// idx is int32 (JAX downcasts int64 without x64).
//
// TWO-PASS INDEX-RANGE PARTITIONING:
//   pass 0 processes rows with idx in [0, 50000), pass 1 with [50000, 100000).
//   Each pass's live table slice is ~29 MB (vs 58 MB) -> ~23% of the 126 MB
//   L2, ~5 touches per line per pass -> gather hit rate ~100%, cutting the
//   ~178 MB/launch of table re-reads that the 612 MB store stream causes.
// Per warp: 4 rows, one int4 idx broadcast, all in-range gathers issued
// before any store (MLP). Stores: __stcs float2 (8B-aligned 584 B rows,
// evict-first streaming; R5-proven best store policy).

#define ROWS_PER_WARP 4
#define SPLIT_ITEM 50000

__global__ void __launch_bounds__(256)
item_gather_concat_kernel(const int*    __restrict__ idx,
                          const float4* __restrict__ emb,   // [N, 32] float4
                          const float2* __restrict__ gen,   // [N, 9]  float2
                          float2*       __restrict__ out,   // [B, 73] float2
                          int B, int loItem, int hiItem)
{
    const int lane  = threadIdx.x & 31;
    const int gwarp = (int)((blockIdx.x * (unsigned)blockDim.x + threadIdx.x) >> 5);
    const int r0    = gwarp * ROWS_PER_WARP;

    if (r0 + ROWS_PER_WARP <= B) {
        int4 iv = __ldcs((const int4*)(idx + r0));   // read-once broadcast
        int items[4] = {iv.x, iv.y, iv.z, iv.w};
        bool act[4];
        #pragma unroll
        for (int j = 0; j < 4; j++)
            act[j] = (items[j] >= loItem) && (items[j] < hiItem);

        // Issue all in-range gathers first (MLP), then store.
        float4 e[4];
        float2 g[4];
        #pragma unroll
        for (int j = 0; j < 4; j++)
            if (act[j])
                e[j] = __ldg(&emb[(size_t)items[j] * 32 + lane]);
        #pragma unroll
        for (int j = 0; j < 4; j++)
            if (act[j] && lane < 9)
                g[j] = __ldg(&gen[(size_t)items[j] * 9 + lane]);

        #pragma unroll
        for (int j = 0; j < 4; j++) {
            if (!act[j]) continue;
            float2* o = out + (size_t)(r0 + j) * 73;   // 8B-aligned rows
            __stcs(&o[lane * 2 + 0], make_float2(e[j].x, e[j].y));
            __stcs(&o[lane * 2 + 1], make_float2(e[j].z, e[j].w));
            if (lane < 9)
                __stcs(&o[64 + lane], g[j]);
        }
    } else {
        // Tail fallback (unused for B = 1M): one row at a time.
        for (int r = r0; r < B && r < r0 + ROWS_PER_WARP; r++) {
            int item = idx[r];
            if (item < loItem || item >= hiItem) continue;
            float4 e = __ldg(&emb[(size_t)item * 32 + lane]);
            float2* o = out + (size_t)r * 73;
            o[lane * 2 + 0] = make_float2(e.x, e.y);
            o[lane * 2 + 1] = make_float2(e.z, e.w);
            if (lane < 9)
                o[64 + lane] = __ldg(&gen[(size_t)item * 9 + lane]);
        }
    }
}

extern "C" void kernel_launch(void* const* d_in, const int* in_sizes, int n_in,
                              void* d_out, int out_size)
{
    const int*    idx = (const int*)   d_in[0];
    const float4* emb = (const float4*)d_in[1];
    const float2* gen = (const float2*)d_in[2];
    float2*       out = (float2*)d_out;

    int B = in_sizes[0];                                   // 1048576
    int rowsPerBlock = 8 * ROWS_PER_WARP;                  // 8 warps/block
    int blocks = (B + rowsPerBlock - 1) / rowsPerBlock;    // 32768

    item_gather_concat_kernel<<<blocks, 256>>>(idx, emb, gen, out, B,
                                               0, SPLIT_ITEM);
    item_gather_concat_kernel<<<blocks, 256>>>(idx, emb, gen, out, B,
                                               SPLIT_ITEM, 0x7FFFFFFF);
}

// round 11
// speedup vs baseline: 1.2074x; 1.2074x over previous
#include <cuda_runtime.h>
#include <cstdint>

// out[b, 0:128]   = emb[idx[b], :]    (128 f32)
// out[b, 128:146] = genre[idx[b], :]  (18 f32)
// idx is int32 (JAX downcasts int64 without x64).
//
// Gathers via cp.async (LDGSTS): register-free outstanding loads.
// Warp handles 8 rows: per row each lane issues one 16B cp.async.cg for the
// emb row (32 lanes x 16B = 512 B) and lanes 0..8 one 8B cp.async.ca for
// genre -> 16 outstanding loads/warp with regs ~36, occ ~75% (smem-limited:
// 37.9 KB/block, 6 blocks/SM). Bytes-in-flight/SM ~200 KB >> lat*BW (~14 KB)
// so gather latency cannot bind; this probes the true HBM R/W-mix ceiling.
// .cg bypasses L1 (no staging tax); each lane reads back only its own smem
// bytes, so cp.async.wait_group 0 alone orders it (no barrier needed).
// Stores: __stcs float2 direct (R5-proven).

#define ROWS_PER_WARP 8
#define WARP_SMEM_FLOATS (8 * 128 + 8 * 20)   // 1184 floats = 4736 B per warp
#define BLOCK_SMEM_FLOATS (8 * WARP_SMEM_FLOATS)

__device__ __forceinline__ unsigned smem_u32(const void* p) {
    return (unsigned)__cvta_generic_to_shared(p);
}

__global__ void __launch_bounds__(256)
item_gather_concat_kernel(const int*    __restrict__ idx,
                          const float4* __restrict__ emb,   // [N, 32] float4
                          const float2* __restrict__ gen,   // [N, 9]  float2
                          float2*       __restrict__ out,   // [B, 73] float2
                          int B)
{
    __shared__ float s[BLOCK_SMEM_FLOATS];

    const int lane  = threadIdx.x & 31;
    const int w     = threadIdx.x >> 5;
    const int gwarp = (int)((blockIdx.x * (unsigned)blockDim.x + threadIdx.x) >> 5);
    const int r0    = gwarp * ROWS_PER_WARP;

    float* sw = s + w * WARP_SMEM_FLOATS;          // this warp's staging area

    if (r0 + ROWS_PER_WARP <= B) {
        int4 iv0 = __ldcs((const int4*)(idx + r0));
        int4 iv1 = __ldcs((const int4*)(idx + r0 + 4));
        int items[8] = {iv0.x, iv0.y, iv0.z, iv0.w,
                        iv1.x, iv1.y, iv1.z, iv1.w};

        // Issue all gathers as cp.async (no dest registers -> huge MLP).
        #pragma unroll
        for (int j = 0; j < 8; j++) {
            unsigned dst = smem_u32(sw + j * 128 + lane * 4);
            const float4* src = &emb[(size_t)items[j] * 32 + lane];
            asm volatile("cp.async.cg.shared.global [%0], [%1], 16;"
                         :: "r"(dst), "l"(src));
        }
        if (lane < 9) {
            #pragma unroll
            for (int j = 0; j < 8; j++) {
                unsigned dst = smem_u32(sw + 1024 + j * 20 + lane * 2);
                const float2* src = &gen[(size_t)items[j] * 9 + lane];
                asm volatile("cp.async.ca.shared.global [%0], [%1], 8;"
                             :: "r"(dst), "l"(src));
            }
        }
        asm volatile("cp.async.commit_group;");
        asm volatile("cp.async.wait_group 0;");

        // Each lane reads back exactly the bytes its own cp.asyncs wrote.
        #pragma unroll
        for (int j = 0; j < 8; j++) {
            float4 e = *(const float4*)(sw + j * 128 + lane * 4);
            float2* o = out + (size_t)(r0 + j) * 73;    // 8B-aligned rows
            __stcs(&o[lane * 2 + 0], make_float2(e.x, e.y));
            __stcs(&o[lane * 2 + 1], make_float2(e.z, e.w));
            if (lane < 9) {
                float2 g = *(const float2*)(sw + 1024 + j * 20 + lane * 2);
                __stcs(&o[64 + lane], g);
            }
        }
    } else {
        // Tail fallback (unused for B = 1M): one row at a time.
        for (int r = r0; r < B && r < r0 + ROWS_PER_WARP; r++) {
            int item = idx[r];
            float4 e = __ldg(&emb[(size_t)item * 32 + lane]);
            float2* o = out + (size_t)r * 73;
            o[lane * 2 + 0] = make_float2(e.x, e.y);
            o[lane * 2 + 1] = make_float2(e.z, e.w);
            if (lane < 9)
                o[64 + lane] = __ldg(&gen[(size_t)item * 9 + lane]);
        }
    }
}

extern "C" void kernel_launch(void* const* d_in, const int* in_sizes, int n_in,
                              void* d_out, int out_size)
{
    const int*    idx = (const int*)   d_in[0];
    const float4* emb = (const float4*)d_in[1];
    const float2* gen = (const float2*)d_in[2];
    float2*       out = (float2*)d_out;

    int B = in_sizes[0];                                   // 1048576
    int rowsPerBlock = 8 * ROWS_PER_WARP;                  // 64 rows/block
    int blocks = (B + rowsPerBlock - 1) / rowsPerBlock;    // 16384

    item_gather_concat_kernel<<<blocks, 256>>>(idx, emb, gen, out, B);
}